// round 1
// baseline (speedup 1.0000x reference)
#include <cuda_runtime.h>

// LDDMM Hamiltonian evolve, B=1, N=8192, D=3, sigma=0.1
// out[0 : 3N]   = -dH/dq = 400 * sum_j K_ij * <p_i,p_j> * (q_i - q_j)
// out[3N : 6N]  =  dH/dp = 2   * sum_j K_ij * p_j
// K_ij = exp(-|q_i-q_j|^2 * 100)

#define NPTS 8192
#define TI 256           // threads per CTA (= i-tile)
#define JSPLIT 16        // j-dimension partitions
#define JC (NPTS / JSPLIT) // 512 j per CTA

// Deterministic two-pass reduction scratch: [JSPLIT][NPTS][6]
__device__ float g_part[(size_t)JSPLIT * NPTS * 6];

__device__ __forceinline__ float fast_ex2(float x) {
    float y;
    asm("ex2.approx.ftz.f32 %0, %1;" : "=f"(y) : "f"(x));
    return y;
}

__global__ __launch_bounds__(TI)
void lddmm_partial_kernel(const float* __restrict__ mom,
                          const float* __restrict__ q) {
    // j-tile in smem, padded to 8 floats/point for aligned float4 loads
    __shared__ __align__(16) float s[JC * 8];

    const int js = blockIdx.y;
    const int jbase = js * JC;

    for (int t = threadIdx.x; t < JC; t += TI) {
        const int gj = jbase + t;
        s[t * 8 + 0] = q[gj * 3 + 0];
        s[t * 8 + 1] = q[gj * 3 + 1];
        s[t * 8 + 2] = q[gj * 3 + 2];
        s[t * 8 + 3] = 0.0f;
        s[t * 8 + 4] = mom[gj * 3 + 0];
        s[t * 8 + 5] = mom[gj * 3 + 1];
        s[t * 8 + 6] = mom[gj * 3 + 2];
        s[t * 8 + 7] = 0.0f;
    }
    __syncthreads();

    const int i = blockIdx.x * TI + threadIdx.x;
    const float qx = q[i * 3 + 0], qy = q[i * 3 + 1], qz = q[i * 3 + 2];
    const float px = mom[i * 3 + 0], py = mom[i * 3 + 1], pz = mom[i * 3 + 2];

    float a0 = 0.f, a1 = 0.f, a2 = 0.f;   // sum K*pd*(qi-qj)   (unscaled)
    float b0 = 0.f, b1 = 0.f, b2 = 0.f;   // sum K*pj           (unscaled)

    // -100 / sigma^2 folded with log2(e) for a single EX2:
    // exp(-100*d2) = exp2(d2 * (-100*log2 e))
    const float C = -144.26950408889634f;

#pragma unroll 4
    for (int j = 0; j < JC; j++) {
        const float4 v0 = *reinterpret_cast<const float4*>(&s[j * 8]);      // q_j
        const float4 v1 = *reinterpret_cast<const float4*>(&s[j * 8 + 4]);  // p_j

        const float dx = qx - v0.x;
        const float dy = qy - v0.y;
        const float dz = qz - v0.z;
        const float d2 = fmaf(dx, dx, fmaf(dy, dy, dz * dz));
        const float K  = fast_ex2(d2 * C);

        const float pd = fmaf(px, v1.x, fmaf(py, v1.y, pz * v1.z));

        b0 = fmaf(K, v1.x, b0);
        b1 = fmaf(K, v1.y, b1);
        b2 = fmaf(K, v1.z, b2);

        const float w = K * pd;
        a0 = fmaf(w, dx, a0);
        a1 = fmaf(w, dy, a1);
        a2 = fmaf(w, dz, a2);
    }

    float* gp = &g_part[((size_t)js * NPTS + i) * 6];
    gp[0] = a0; gp[1] = a1; gp[2] = a2;
    gp[3] = b0; gp[4] = b1; gp[5] = b2;
}

__global__ void lddmm_reduce_kernel(float* __restrict__ out) {
    const int t = blockIdx.x * blockDim.x + threadIdx.x;
    if (t >= NPTS * 3) return;
    const int i = t / 3;
    const int c = t % 3;

    float s1 = 0.f, s2 = 0.f;
#pragma unroll
    for (int js = 0; js < JSPLIT; js++) {
        const float* gp = &g_part[((size_t)js * NPTS + i) * 6];
        s1 += gp[c];
        s2 += gp[3 + c];
    }
    out[t] = 400.0f * s1;            // -dH/dq
    out[NPTS * 3 + t] = 2.0f * s2;   //  dH/dp
}

extern "C" void kernel_launch(void* const* d_in, const int* in_sizes, int n_in,
                              void* d_out, int out_size) {
    const float* mom = (const float*)d_in[0];            // [1,8192,3]
    const float* control_points = (const float*)d_in[1]; // [1,8192,3]
    float* out = (float*)d_out;                          // [2*8192*3]

    dim3 grid(NPTS / TI, JSPLIT);
    lddmm_partial_kernel<<<grid, TI>>>(mom, control_points);

    const int rthreads = 256;
    const int rtotal = NPTS * 3;
    lddmm_reduce_kernel<<<(rtotal + rthreads - 1) / rthreads, rthreads>>>(out);
}

// round 2
// speedup vs baseline: 1.2232x; 1.2232x over previous
#include <cuda_runtime.h>

// LDDMM Hamiltonian evolve, B=1, N=8192, D=3, sigma=0.1
// out[0 : 3N]   = -dH/dq = 400 * sum_j K_ij * <p_i,p_j> * (q_i - q_j)
// out[3N : 6N]  =  dH/dp = 2   * sum_j K_ij * p_j
// K_ij = exp(-100*|q_i-q_j|^2) = exp2(C*d2), C = -100*log2(e)
//
// Packed f32x2 mainloop: each fma-pipe instruction processes TWO j-points.

#define NPTS 8192
#define TI 128             // threads per CTA (i-tile)
#define JSPLIT 16          // j-dimension partitions
#define JC (NPTS / JSPLIT) // 512 j per CTA
#define JPAIRS (JC / 2)    // 256 packed pairs

// Deterministic two-pass reduction scratch: [JSPLIT][NPTS][6]
__device__ float g_part[(size_t)JSPLIT * NPTS * 6];

typedef unsigned long long u64;

__device__ __forceinline__ u64 pack2(float lo, float hi) {
    u64 r; asm("mov.b64 %0, {%1, %2};" : "=l"(r) : "f"(lo), "f"(hi)); return r;
}
__device__ __forceinline__ void unpack2(u64 v, float& lo, float& hi) {
    asm("mov.b64 {%0, %1}, %2;" : "=f"(lo), "=f"(hi) : "l"(v));
}
__device__ __forceinline__ u64 fma2(u64 a, u64 b, u64 c) {
    u64 r; asm("fma.rn.f32x2 %0, %1, %2, %3;" : "=l"(r) : "l"(a), "l"(b), "l"(c)); return r;
}
__device__ __forceinline__ u64 add2(u64 a, u64 b) {
    u64 r; asm("add.rn.f32x2 %0, %1, %2;" : "=l"(r) : "l"(a), "l"(b)); return r;
}
__device__ __forceinline__ u64 mul2(u64 a, u64 b) {
    u64 r; asm("mul.rn.f32x2 %0, %1, %2;" : "=l"(r) : "l"(a), "l"(b)); return r;
}
__device__ __forceinline__ u64 ex2_2(u64 x) {
    u64 r;
    asm("{\n\t"
        ".reg .f32 l, h;\n\t"
        "mov.b64 {l, h}, %1;\n\t"
        "ex2.approx.ftz.f32 l, l;\n\t"
        "ex2.approx.ftz.f32 h, h;\n\t"
        "mov.b64 %0, {l, h};\n\t"
        "}" : "=l"(r) : "l"(x));
    return r;
}

__global__ __launch_bounds__(TI, 8)
void lddmm_partial_kernel(const float* __restrict__ mom,
                          const float* __restrict__ q) {
    // Per j-pair: 6 packed u64: [-qx | -qy | -qz | px | py | pz] (48B)
    __shared__ __align__(16) u64 s[JPAIRS * 6];

    const int js = blockIdx.y;
    const int jbase = js * JC;

    for (int p = threadIdx.x; p < JPAIRS; p += TI) {
        const int j0 = jbase + 2 * p;
        const int j1 = j0 + 1;
        s[p * 6 + 0] = pack2(-q[j0 * 3 + 0], -q[j1 * 3 + 0]);
        s[p * 6 + 1] = pack2(-q[j0 * 3 + 1], -q[j1 * 3 + 1]);
        s[p * 6 + 2] = pack2(-q[j0 * 3 + 2], -q[j1 * 3 + 2]);
        s[p * 6 + 3] = pack2(mom[j0 * 3 + 0], mom[j1 * 3 + 0]);
        s[p * 6 + 4] = pack2(mom[j0 * 3 + 1], mom[j1 * 3 + 1]);
        s[p * 6 + 5] = pack2(mom[j0 * 3 + 2], mom[j1 * 3 + 2]);
    }
    __syncthreads();

    const int i = blockIdx.x * TI + threadIdx.x;
    const float qx = q[i * 3 + 0], qy = q[i * 3 + 1], qz = q[i * 3 + 2];
    const float px = mom[i * 3 + 0], py = mom[i * 3 + 1], pz = mom[i * 3 + 2];

    // Broadcast packed i-values
    const u64 qxx = pack2(qx, qx), qyy = pack2(qy, qy), qzz = pack2(qz, qz);
    const u64 pxx = pack2(px, px), pyy = pack2(py, py), pzz = pack2(pz, pz);
    const float Cs = -144.26950408889634f;   // -100 * log2(e)
    const u64 Cp = pack2(Cs, Cs);

    u64 a0 = 0, a1 = 0, a2 = 0;  // sum K*pd*(qi-qj), packed halves
    u64 b0 = 0, b1 = 0, b2 = 0;  // sum K*pj, packed halves

#pragma unroll 4
    for (int p = 0; p < JPAIRS; p++) {
        // ld.shared.v2.u64 x3 -> six aligned b64 register pairs, broadcast
        const ulonglong2 w0 = *reinterpret_cast<const ulonglong2*>(&s[p * 6 + 0]);
        const ulonglong2 w1 = *reinterpret_cast<const ulonglong2*>(&s[p * 6 + 2]);
        const ulonglong2 w2 = *reinterpret_cast<const ulonglong2*>(&s[p * 6 + 4]);
        const u64 nqx = w0.x, nqy = w0.y, nqz = w1.x;
        const u64 pjx = w1.y, pjy = w2.x, pjz = w2.y;

        const u64 dx = add2(qxx, nqx);
        const u64 dy = add2(qyy, nqy);
        const u64 dz = add2(qzz, nqz);
        const u64 d2 = fma2(dx, dx, fma2(dy, dy, mul2(dz, dz)));
        const u64 K  = ex2_2(mul2(d2, Cp));

        const u64 pd = fma2(pxx, pjx, fma2(pyy, pjy, mul2(pzz, pjz)));

        b0 = fma2(K, pjx, b0);
        b1 = fma2(K, pjy, b1);
        b2 = fma2(K, pjz, b2);

        const u64 w = mul2(K, pd);
        a0 = fma2(w, dx, a0);
        a1 = fma2(w, dy, a1);
        a2 = fma2(w, dz, a2);
    }

    float l, h;
    float* gp = &g_part[((size_t)js * NPTS + i) * 6];
    unpack2(a0, l, h); gp[0] = l + h;
    unpack2(a1, l, h); gp[1] = l + h;
    unpack2(a2, l, h); gp[2] = l + h;
    unpack2(b0, l, h); gp[3] = l + h;
    unpack2(b1, l, h); gp[4] = l + h;
    unpack2(b2, l, h); gp[5] = l + h;
}

__global__ __launch_bounds__(128)
void lddmm_reduce_kernel(float* __restrict__ out) {
    const int t = blockIdx.x * blockDim.x + threadIdx.x;
    if (t >= NPTS * 3) return;
    const int i = t / 3;
    const int c = t % 3;

    float s1 = 0.f, s2 = 0.f;
#pragma unroll
    for (int js = 0; js < JSPLIT; js++) {
        const float* gp = &g_part[((size_t)js * NPTS + i) * 6];
        s1 += gp[c];
        s2 += gp[3 + c];
    }
    out[t] = 400.0f * s1;            // -dH/dq
    out[NPTS * 3 + t] = 2.0f * s2;   //  dH/dp
}

extern "C" void kernel_launch(void* const* d_in, const int* in_sizes, int n_in,
                              void* d_out, int out_size) {
    const float* mom = (const float*)d_in[0];            // [1,8192,3]
    const float* control_points = (const float*)d_in[1]; // [1,8192,3]
    float* out = (float*)d_out;                          // [2*8192*3]

    dim3 grid(NPTS / TI, JSPLIT);
    lddmm_partial_kernel<<<grid, TI>>>(mom, control_points);

    const int rthreads = 128;
    const int rtotal = NPTS * 3;
    lddmm_reduce_kernel<<<(rtotal + rthreads - 1) / rthreads, rthreads>>>(out);
}

// round 3
// speedup vs baseline: 1.3138x; 1.0741x over previous
#include <cuda_runtime.h>

// LDDMM Hamiltonian evolve, B=1, N=8192, D=3, sigma=0.1
// out[0 : 3N]   = -dH/dq = 400 * sum_j K_ij * <p_i,p_j> * (q_i - q_j)
// out[3N : 6N]  =  dH/dp = 2   * sum_j K_ij * p_j
// K_ij = exp(-100*|q_i-q_j|^2) = exp2(C*d2), C = -100*log2(e)
//
// d2 expanded via norms (coords centered at 0.5):
//   K_ij = E_i * exp2( s_j + cq_j . m2q_i ),  E_i = exp2(C*|cq_i|^2),
//   s_j = C*|cq_j|^2 (smem seed),  m2q_i = -2C*cq_i (per-thread consts)
// -> 14 packed f32x2 fma-pipe ops per 2 j-points.

#define NPTS 8192
#define TI 128             // threads per CTA (i-tile)
#define JSPLIT 16          // j-dimension partitions
#define JC (NPTS / JSPLIT) // 512 j per CTA
#define JPAIRS (JC / 2)    // 256 packed pairs
#define HALFSZ (NPTS * 3)  // 24576 floats per output half
#define PLANE (2 * HALFSZ) // 49152 floats per js-plane

// Deterministic two-pass reduction scratch: [JSPLIT][PLANE]
__device__ float g_part[(size_t)JSPLIT * PLANE];

typedef unsigned long long u64;

__device__ __forceinline__ u64 pack2(float lo, float hi) {
    u64 r; asm("mov.b64 %0, {%1, %2};" : "=l"(r) : "f"(lo), "f"(hi)); return r;
}
__device__ __forceinline__ void unpack2(u64 v, float& lo, float& hi) {
    asm("mov.b64 {%0, %1}, %2;" : "=f"(lo), "=f"(hi) : "l"(v));
}
__device__ __forceinline__ u64 fma2(u64 a, u64 b, u64 c) {
    u64 r; asm("fma.rn.f32x2 %0, %1, %2, %3;" : "=l"(r) : "l"(a), "l"(b), "l"(c)); return r;
}
__device__ __forceinline__ u64 add2(u64 a, u64 b) {
    u64 r; asm("add.rn.f32x2 %0, %1, %2;" : "=l"(r) : "l"(a), "l"(b)); return r;
}
__device__ __forceinline__ u64 mul2(u64 a, u64 b) {
    u64 r; asm("mul.rn.f32x2 %0, %1, %2;" : "=l"(r) : "l"(a), "l"(b)); return r;
}
__device__ __forceinline__ u64 ex2_2(u64 x) {
    u64 r;
    asm("{\n\t"
        ".reg .f32 l, h;\n\t"
        "mov.b64 {l, h}, %1;\n\t"
        "ex2.approx.ftz.f32 l, l;\n\t"
        "ex2.approx.ftz.f32 h, h;\n\t"
        "mov.b64 %0, {l, h};\n\t"
        "}" : "=l"(r) : "l"(x));
    return r;
}
__device__ __forceinline__ float fast_ex2(float x) {
    float y; asm("ex2.approx.ftz.f32 %0, %1;" : "=f"(y) : "f"(x)); return y;
}

#define CKER (-144.26950408889634f)   // -100 * log2(e)

__global__ __launch_bounds__(TI, 8)
void lddmm_partial_kernel(const float* __restrict__ mom,
                          const float* __restrict__ q) {
    // Per j-pair: 8 packed u64: [cqx|cqy|cqz|sj|pjx|pjy|pjz|pad] (64B)
    __shared__ __align__(16) u64 s[JPAIRS * 8];

    const int js = blockIdx.y;
    const int jbase = js * JC;

    for (int p = threadIdx.x; p < JPAIRS; p += TI) {
        const int j0 = jbase + 2 * p;
        const int j1 = j0 + 1;
        const float x0 = q[j0 * 3 + 0] - 0.5f, x1 = q[j1 * 3 + 0] - 0.5f;
        const float y0 = q[j0 * 3 + 1] - 0.5f, y1 = q[j1 * 3 + 1] - 0.5f;
        const float z0 = q[j0 * 3 + 2] - 0.5f, z1 = q[j1 * 3 + 2] - 0.5f;
        const float s0 = CKER * (x0 * x0 + y0 * y0 + z0 * z0);
        const float s1 = CKER * (x1 * x1 + y1 * y1 + z1 * z1);
        s[p * 8 + 0] = pack2(x0, x1);
        s[p * 8 + 1] = pack2(y0, y1);
        s[p * 8 + 2] = pack2(z0, z1);
        s[p * 8 + 3] = pack2(s0, s1);
        s[p * 8 + 4] = pack2(mom[j0 * 3 + 0], mom[j1 * 3 + 0]);
        s[p * 8 + 5] = pack2(mom[j0 * 3 + 1], mom[j1 * 3 + 1]);
        s[p * 8 + 6] = pack2(mom[j0 * 3 + 2], mom[j1 * 3 + 2]);
        s[p * 8 + 7] = 0;
    }
    __syncthreads();

    const int i = blockIdx.x * TI + threadIdx.x;
    const float cqx = q[i * 3 + 0] - 0.5f;
    const float cqy = q[i * 3 + 1] - 0.5f;
    const float cqz = q[i * 3 + 2] - 0.5f;
    const float px = mom[i * 3 + 0], py = mom[i * 3 + 1], pz = mom[i * 3 + 2];

    // Per-thread packed broadcast constants
    const float m2x = -2.0f * CKER * cqx;
    const float m2y = -2.0f * CKER * cqy;
    const float m2z = -2.0f * CKER * cqz;
    const u64 M2X = pack2(m2x, m2x), M2Y = pack2(m2y, m2y), M2Z = pack2(m2z, m2z);
    const u64 PXX = pack2(px, px), PYY = pack2(py, py), PZZ = pack2(pz, pz);

    u64 B0 = 0, B1 = 0, B2 = 0;  // sum K' * p_j
    u64 A0 = 0, A1 = 0, A2 = 0;  // sum w' * cq_j
    u64 W  = 0;                   // sum w'          (w' = K'*<p_i,p_j>)

#pragma unroll 4
    for (int p = 0; p < JPAIRS; p++) {
        const ulonglong2 w0 = *reinterpret_cast<const ulonglong2*>(&s[p * 8 + 0]);
        const ulonglong2 w1 = *reinterpret_cast<const ulonglong2*>(&s[p * 8 + 2]);
        const ulonglong2 w2 = *reinterpret_cast<const ulonglong2*>(&s[p * 8 + 4]);
        const ulonglong2 w3 = *reinterpret_cast<const ulonglong2*>(&s[p * 8 + 6]);
        const u64 jx = w0.x, jy = w0.y, jz = w1.x, sj = w1.y;
        const u64 mx = w2.x, my = w2.y, mz = w3.x;

        // arg' = s_j + cq_j . m2q_i   (3 fma, seed straight from smem)
        u64 t = fma2(jx, M2X, sj);
        t = fma2(jy, M2Y, t);
        t = fma2(jz, M2Z, t);
        const u64 K = ex2_2(t);                                   // K' (MUFU x2)

        const u64 pd = fma2(PXX, mx, fma2(PYY, my, mul2(PZZ, mz))); // 3

        B0 = fma2(K, mx, B0);                                     // 3
        B1 = fma2(K, my, B1);
        B2 = fma2(K, mz, B2);

        const u64 w = mul2(K, pd);                                // 1
        W  = add2(W, w);                                          // 1
        A0 = fma2(w, jx, A0);                                     // 3
        A1 = fma2(w, jy, A1);
        A2 = fma2(w, jz, A2);
    }

    // Epilogue: fold E_i = exp2(C*|cq_i|^2) and output scales.
    const float Ei = fast_ex2(CKER * (cqx * cqx + cqy * cqy + cqz * cqz));
    const float eq = 400.0f * Ei;   // scale for -dH/dq
    const float ep = 2.0f * Ei;     // scale for  dH/dp

    float l, h, Ws, A0s, A1s, A2s, B0s, B1s, B2s;
    unpack2(W,  l, h); Ws  = l + h;
    unpack2(A0, l, h); A0s = l + h;
    unpack2(A1, l, h); A1s = l + h;
    unpack2(A2, l, h); A2s = l + h;
    unpack2(B0, l, h); B0s = l + h;
    unpack2(B1, l, h); B1s = l + h;
    unpack2(B2, l, h); B2s = l + h;

    float* gp = &g_part[(size_t)js * PLANE];
    gp[i * 3 + 0] = eq * fmaf(Ws, cqx, -A0s);
    gp[i * 3 + 1] = eq * fmaf(Ws, cqy, -A1s);
    gp[i * 3 + 2] = eq * fmaf(Ws, cqz, -A2s);
    gp[HALFSZ + i * 3 + 0] = ep * B0s;
    gp[HALFSZ + i * 3 + 1] = ep * B1s;
    gp[HALFSZ + i * 3 + 2] = ep * B2s;
}

__global__ __launch_bounds__(256)
void lddmm_reduce_kernel(float* __restrict__ out) {
    const int t = blockIdx.x * blockDim.x + threadIdx.x;
    if (t >= PLANE) return;
    float s = 0.f;
#pragma unroll
    for (int js = 0; js < JSPLIT; js++)
        s += g_part[(size_t)js * PLANE + t];
    out[t] = s;
}

extern "C" void kernel_launch(void* const* d_in, const int* in_sizes, int n_in,
                              void* d_out, int out_size) {
    const float* mom = (const float*)d_in[0];            // [1,8192,3]
    const float* control_points = (const float*)d_in[1]; // [1,8192,3]
    float* out = (float*)d_out;                          // [2*8192*3]

    dim3 grid(NPTS / TI, JSPLIT);
    lddmm_partial_kernel<<<grid, TI>>>(mom, control_points);

    lddmm_reduce_kernel<<<PLANE / 256, 256>>>(out);
}